// round 1
// baseline (speedup 1.0000x reference)
#include <cuda_runtime.h>
#include <math.h>

#define Bn 4
#define Cn 512
#define Ln 4096
#define CKn 64
#define CGn 256

// Scratch (allocation-free rule: static __device__ arrays)
__device__ float g_theta[Bn * Ln * CKn];
__device__ float g_phi[Bn * Ln * CKn];
__device__ float g_gv[Bn * Ln * CGn];
__device__ float g_S[(size_t)Bn * Ln * Ln];      // 268 MB score/prob matrix
__device__ float g_colinv[Bn * Ln];
__device__ float g_ag[Bn * Ln * CGn];

// ---------------------------------------------------------------------------
// K1: fused theta/phi/g projections.  Y[l,o] = sum_c x[b,c,l] * W[o,c] + bias
// grid (L/64, 6, B): group 0=theta(tanh), 1=phi(tanh), 2..5=g slabs of 64
// ---------------------------------------------------------------------------
__global__ void proj_kernel(const float* __restrict__ x,
                            const float* __restrict__ Wt, const float* __restrict__ bt,
                            const float* __restrict__ Wp, const float* __restrict__ bp,
                            const float* __restrict__ Wg, const float* __restrict__ bg) {
    int m0 = blockIdx.x * 64;
    int grp = blockIdx.y;
    int b = blockIdx.z;
    int tid = threadIdx.x;
    int tx = tid & 15, ty = tid >> 4;   // tx -> out channel, ty -> pixel l

    const float* W; const float* bias; float* outp; int ldo; int ob; bool do_tanh;
    if (grp == 0)      { W = Wt; bias = bt; outp = g_theta + (size_t)b * Ln * CKn; ldo = CKn; ob = 0; do_tanh = true; }
    else if (grp == 1) { W = Wp; bias = bp; outp = g_phi + (size_t)b * Ln * CKn; ldo = CKn; ob = 0; do_tanh = true; }
    else { W = Wg + (size_t)(grp - 2) * 64 * Cn; bias = bg + (grp - 2) * 64;
           outp = g_gv + (size_t)b * Ln * CGn; ldo = CGn; ob = (grp - 2) * 64; do_tanh = false; }

    __shared__ float xs[32][64];    // [k][l]
    __shared__ float ws[64][33];    // [o][k]

    float acc[4][4];
#pragma unroll
    for (int i = 0; i < 4; i++)
#pragma unroll
        for (int j = 0; j < 4; j++) acc[i][j] = 0.f;

    const float* xb = x + (size_t)b * Cn * Ln;

    for (int k0 = 0; k0 < Cn; k0 += 32) {
#pragma unroll
        for (int i = 0; i < 8; i++) {
            int idx = tid + i * 256;
            int r = idx >> 6, c = idx & 63;
            xs[r][c] = xb[(size_t)(k0 + r) * Ln + m0 + c];
        }
#pragma unroll
        for (int i = 0; i < 8; i++) {
            int idx = tid + i * 256;
            int r = idx >> 5, c = idx & 31;
            ws[r][c] = W[(size_t)r * Cn + k0 + c];
        }
        __syncthreads();
#pragma unroll
        for (int kk = 0; kk < 32; kk++) {
            float a[4], w[4];
#pragma unroll
            for (int i = 0; i < 4; i++) a[i] = xs[kk][ty * 4 + i];
#pragma unroll
            for (int j = 0; j < 4; j++) w[j] = ws[tx * 4 + j][kk];
#pragma unroll
            for (int i = 0; i < 4; i++)
#pragma unroll
                for (int j = 0; j < 4; j++) acc[i][j] += a[i] * w[j];
        }
        __syncthreads();
    }
#pragma unroll
    for (int j = 0; j < 4; j++) {
        float bv = bias[tx * 4 + j];
#pragma unroll
        for (int i = 0; i < 4; i++) {
            float v = acc[i][j] + bv;
            if (do_tanh) v = tanhf(v);
            outp[(size_t)(m0 + ty * 4 + i) * ldo + ob + tx * 4 + j] = v;
        }
    }
}

// ---------------------------------------------------------------------------
// K2: S[l,m] = theta[l,:] . phi[m,:]   (K = 64, single tile load)
// grid (L/64, L/64, B)
// ---------------------------------------------------------------------------
__global__ void scores_kernel() {
    int m0 = blockIdx.x * 64;
    int l0 = blockIdx.y * 64;
    int b = blockIdx.z;
    int tid = threadIdx.x;
    int tx = tid & 15, ty = tid >> 4;   // tx -> m (coalesced stores), ty -> l

    __shared__ float ts[64][65];
    __shared__ float ps[64][65];

    const float* th = g_theta + (size_t)b * Ln * CKn;
    const float* ph = g_phi + (size_t)b * Ln * CKn;
#pragma unroll
    for (int i = 0; i < 16; i++) {
        int idx = tid + i * 256;
        int r = idx >> 6, k = idx & 63;
        ts[r][k] = th[(size_t)(l0 + r) * CKn + k];
        ps[r][k] = ph[(size_t)(m0 + r) * CKn + k];
    }
    __syncthreads();
    float acc[4][4] = {};
#pragma unroll
    for (int kk = 0; kk < 64; kk++) {
        float a[4], c[4];
#pragma unroll
        for (int i = 0; i < 4; i++) a[i] = ts[ty * 4 + i][kk];
#pragma unroll
        for (int j = 0; j < 4; j++) c[j] = ps[tx * 4 + j][kk];
#pragma unroll
        for (int i = 0; i < 4; i++)
#pragma unroll
            for (int j = 0; j < 4; j++) acc[i][j] += a[i] * c[j];
    }
    float* Sb = g_S + (size_t)b * Ln * Ln;
#pragma unroll
    for (int i = 0; i < 4; i++) {
        float4 v = make_float4(acc[i][0], acc[i][1], acc[i][2], acc[i][3]);
        *reinterpret_cast<float4*>(&Sb[(size_t)(l0 + ty * 4 + i) * Ln + m0 + tx * 4]) = v;
    }
}

// ---------------------------------------------------------------------------
// K3: column softmax stats (softmax over QUERY axis l, per column m).
// Pass 1: max over l.  Pass 2: write exp(v-max) back in-place, accumulate sum.
// grid (L/256, B)
// ---------------------------------------------------------------------------
__global__ void colstats_kernel() {
    int b = blockIdx.y;
    int m = blockIdx.x * 256 + threadIdx.x;
    float* Sb = g_S + (size_t)b * Ln * Ln;
    float mx = -1e30f;
    for (int l = 0; l < Ln; l += 4) {
        size_t base = (size_t)l * Ln + m;
        float v0 = Sb[base];
        float v1 = Sb[base + Ln];
        float v2 = Sb[base + 2 * (size_t)Ln];
        float v3 = Sb[base + 3 * (size_t)Ln];
        mx = fmaxf(mx, fmaxf(fmaxf(v0, v1), fmaxf(v2, v3)));
    }
    float sum = 0.f;
    for (int l = 0; l < Ln; l += 4) {
        size_t base = (size_t)l * Ln + m;
        float e0 = __expf(Sb[base] - mx);
        float e1 = __expf(Sb[base + Ln] - mx);
        float e2 = __expf(Sb[base + 2 * (size_t)Ln] - mx);
        float e3 = __expf(Sb[base + 3 * (size_t)Ln] - mx);
        Sb[base] = e0;
        Sb[base + Ln] = e1;
        Sb[base + 2 * (size_t)Ln] = e2;
        Sb[base + 3 * (size_t)Ln] = e3;
        sum += e0 + e1 + e2 + e3;
    }
    g_colinv[b * Ln + m] = 1.0f / sum;   // sum >= 1 (max term contributes 1)
}

// ---------------------------------------------------------------------------
// K3c: fold 1/colsum into g rows: g[m,c] *= colinv[m]
// ---------------------------------------------------------------------------
__global__ void scaleg_kernel() {
    int idx = blockIdx.x * 256 + threadIdx.x;   // float4 index
    float4* gp = reinterpret_cast<float4*>(g_gv);
    int e = idx * 4;
    int m = (e / CGn) & (Ln - 1);
    int b = e / (Ln * CGn);
    float s = g_colinv[b * Ln + m];
    float4 v = gp[idx];
    v.x *= s; v.y *= s; v.z *= s; v.w *= s;
    gp[idx] = v;
}

// ---------------------------------------------------------------------------
// K4: AG[l,c] = sum_m P[l,m] * g'[m,c]   (M=4096, N=256, K=4096) -- dominant
// grid (CG/64, L/64, B)
// ---------------------------------------------------------------------------
__global__ void attng_kernel() {
    int n0 = blockIdx.x * 64;
    int l0 = blockIdx.y * 64;
    int b = blockIdx.z;
    int tid = threadIdx.x;
    int tx = tid & 15, ty = tid >> 4;   // tx -> c (coalesced stores), ty -> l

    __shared__ float ps[64][33];   // [l][k]
    __shared__ float gs[32][64];   // [k][c]

    const float* Sb = g_S + (size_t)b * Ln * Ln;
    const float* gb = g_gv + (size_t)b * Ln * CGn;
    float acc[4][4] = {};
    for (int k0 = 0; k0 < Ln; k0 += 32) {
#pragma unroll
        for (int i = 0; i < 8; i++) {
            int idx = tid + i * 256;
            int r = idx >> 5, c = idx & 31;
            ps[r][c] = Sb[(size_t)(l0 + r) * Ln + k0 + c];
        }
#pragma unroll
        for (int i = 0; i < 8; i++) {
            int idx = tid + i * 256;
            int r = idx >> 6, c = idx & 63;
            gs[r][c] = gb[(size_t)(k0 + r) * CGn + n0 + c];
        }
        __syncthreads();
#pragma unroll
        for (int kk = 0; kk < 32; kk++) {
            float p[4], gg[4];
#pragma unroll
            for (int i = 0; i < 4; i++) p[i] = ps[ty * 4 + i][kk];
#pragma unroll
            for (int j = 0; j < 4; j++) gg[j] = gs[kk][tx * 4 + j];
#pragma unroll
            for (int i = 0; i < 4; i++)
#pragma unroll
                for (int j = 0; j < 4; j++) acc[i][j] += p[i] * gg[j];
        }
        __syncthreads();
    }
    float* ag = g_ag + (size_t)b * Ln * CGn;
#pragma unroll
    for (int i = 0; i < 4; i++) {
        float4 v = make_float4(acc[i][0], acc[i][1], acc[i][2], acc[i][3]);
        *reinterpret_cast<float4*>(&ag[(size_t)(l0 + ty * 4 + i) * CGn + n0 + tx * 4]) = v;
    }
}

// ---------------------------------------------------------------------------
// K5: out-projection + residual blend.  v[c2,l] = sum_k Wo[c2,k]*AG[l,k] + bo
// out1 = (1-alpha)*x + alpha*v ; out2 = v.   grid (L/64, C/64, B)
// ---------------------------------------------------------------------------
__global__ void final_kernel(const float* __restrict__ x,
                             const float* __restrict__ Wo, const float* __restrict__ bo,
                             const float* __restrict__ gamma, float* __restrict__ out) {
    int l0 = blockIdx.x * 64;
    int c0 = blockIdx.y * 64;
    int b = blockIdx.z;
    int tid = threadIdx.x;
    int tx = tid & 15, ty = tid >> 4;   // tx -> l (coalesced stores), ty -> c2

    __shared__ float as_[64][65];  // [l][k]
    __shared__ float ws[64][65];   // [c2][k]

    const float* ag = g_ag + (size_t)b * Ln * CGn;
    float acc[4][4] = {};
    for (int k0 = 0; k0 < CGn; k0 += 64) {
#pragma unroll
        for (int i = 0; i < 16; i++) {
            int idx = tid + i * 256;
            int r = idx >> 6, k = idx & 63;
            as_[r][k] = ag[(size_t)(l0 + r) * CGn + k0 + k];
            ws[r][k] = Wo[(size_t)(c0 + r) * CGn + k0 + k];
        }
        __syncthreads();
#pragma unroll
        for (int kk = 0; kk < 64; kk++) {
            float av[4], wv[4];
#pragma unroll
            for (int j = 0; j < 4; j++) av[j] = as_[tx * 4 + j][kk];
#pragma unroll
            for (int i = 0; i < 4; i++) wv[i] = ws[ty * 4 + i][kk];
#pragma unroll
            for (int i = 0; i < 4; i++)
#pragma unroll
                for (int j = 0; j < 4; j++) acc[i][j] += wv[i] * av[j];
        }
        __syncthreads();
    }
    float gv = gamma[0];
    float alpha = 1.0f / (1.0f + __expf(-gv));
    float* out1 = out;
    float* out2 = out + (size_t)Bn * Cn * Ln;
#pragma unroll
    for (int i = 0; i < 4; i++) {
        int c2 = c0 + ty * 4 + i;
        float bv = bo[c2];
        size_t base = (size_t)b * Cn * Ln + (size_t)c2 * Ln + l0 + tx * 4;
        float4 xv = *reinterpret_cast<const float4*>(&x[base]);
        float4 v;
        v.x = acc[i][0] + bv; v.y = acc[i][1] + bv;
        v.z = acc[i][2] + bv; v.w = acc[i][3] + bv;
        *reinterpret_cast<float4*>(&out2[base]) = v;
        float4 o1;
        o1.x = (1.f - alpha) * xv.x + alpha * v.x;
        o1.y = (1.f - alpha) * xv.y + alpha * v.y;
        o1.z = (1.f - alpha) * xv.z + alpha * v.z;
        o1.w = (1.f - alpha) * xv.w + alpha * v.w;
        *reinterpret_cast<float4*>(&out1[base]) = o1;
    }
}

extern "C" void kernel_launch(void* const* d_in, const int* in_sizes, int n_in,
                              void* d_out, int out_size) {
    const float* x     = (const float*)d_in[0];
    const float* Wt    = (const float*)d_in[1];
    const float* bt    = (const float*)d_in[2];
    const float* Wp    = (const float*)d_in[3];
    const float* bp    = (const float*)d_in[4];
    const float* Wg    = (const float*)d_in[5];
    const float* bg    = (const float*)d_in[6];
    const float* Wo    = (const float*)d_in[7];
    const float* bo    = (const float*)d_in[8];
    const float* gamma = (const float*)d_in[9];
    float* out = (float*)d_out;

    proj_kernel<<<dim3(Ln / 64, 6, Bn), 256>>>(x, Wt, bt, Wp, bp, Wg, bg);
    scores_kernel<<<dim3(Ln / 64, Ln / 64, Bn), 256>>>();
    colstats_kernel<<<dim3(Ln / 256, Bn), 256>>>();
    scaleg_kernel<<<(Bn * Ln * CGn / 4) / 256, 256>>>();
    attng_kernel<<<dim3(CGn / 64, Ln / 64, Bn), 256>>>();
    final_kernel<<<dim3(Ln / 64, Cn / 64, Bn), 256>>>(x, Wo, bo, gamma, out);
}